// round 4
// baseline (speedup 1.0000x reference)
#include <cuda_runtime.h>
#include <cstddef>

// SNNLayer: x(16,1024,2048) fp32, weight(1024,1024) fp32, v0(1024) fp32
// einsum('bct,on->bnt') factorizes: inp[b,n,t] = sx[b,t] * cs[n]
//   sx[b,t] = sum_c x[b,c,t]   (sequential-c order, bit-identical since r1)
//   cs[n]   = sum_o w[o,n]     (16 chunks of 64, sequential, as r1)
// LIF: v += (i - v)*0.1 ; spike = v>=1 ; hard reset to exact 0.
// Parallel-in-T: 8 segments x 256 steps, 64-step warm-up from v=0.

#define BB 16
#define CC 1024
#define TT 2048
#define NN 1024
#define OCHUNKS 16
#define OPER    (CC / OCHUNKS)   // 64

#define SEG    8
#define SEGLEN (TT / SEG)        // 256
#define WARM   64
#define TC     32
#define RB     64                // rowsum register-batch depth

__device__ float g_sx[BB * TT];             // 128 KB
__device__ float g_cs_part[OCHUNKS * NN];   // 64 KB

// ---------------------------------------------------------------------------
// Kernel 1: fused rowsum (blocks 0..127) + weight colsum partials (128..191).
// Rowsum: explicit 64-deep register staging forces 64 outstanding LDGs per
// thread before any FADD consumes them (8 KB/warp in flight -> HBM-bound).
// Accumulation order unchanged: strictly sequential in c.
// ---------------------------------------------------------------------------
__global__ void __launch_bounds__(256)
reduce_fused_kernel(const float* __restrict__ x, const float* __restrict__ w) {
    if (blockIdx.x < 128) {
        const int idx = blockIdx.x * 256 + threadIdx.x;   // b*TT + t
        const int b = idx / TT;
        const int t = idx % TT;
        const float* p = x + (size_t)b * CC * TT + t;
        float acc = 0.0f;
        for (int c0 = 0; c0 < CC; c0 += RB) {
            float buf[RB];
#pragma unroll
            for (int i = 0; i < RB; ++i) {
                buf[i] = __ldcs(p + (size_t)(c0 + i) * TT);
            }
#pragma unroll
            for (int i = 0; i < RB; ++i) {
                acc = __fadd_rn(acc, buf[i]);
            }
        }
        g_sx[idx] = acc;
    } else {
        const int bid = blockIdx.x - 128;                 // 0..63
        const int oc  = bid >> 2;                         // 0..15
        const int n   = (bid & 3) * 256 + threadIdx.x;    // 0..1023
        const float* p = w + (size_t)oc * OPER * NN + n;
        float acc = 0.0f;
#pragma unroll 16
        for (int o = 0; o < OPER; ++o) {
            acc = __fadd_rn(acc, p[(size_t)o * NN]);
        }
        g_cs_part[oc * NN + n] = acc;
    }
}

// ---------------------------------------------------------------------------
// Kernel 2: segmented LIF, spikes bit-packed in registers, shuffle transpose,
// nibble->float4 via 16-entry SMEM LUT, STG.128 coalesced writes.
// grid (NN/128, BB, SEG) = 1024 blocks, block 128 (thread = one n).
// ---------------------------------------------------------------------------
__global__ void __launch_bounds__(128)
lif_seg_kernel(const float* __restrict__ v0, float* __restrict__ out) {
    const int tid = threadIdx.x;               // 0..127
    const int n0  = blockIdx.x * 128;
    const int b   = blockIdx.y;
    const int s   = blockIdx.z;
    const int n   = n0 + tid;

    __shared__ float  sxs[WARM + SEGLEN];      // 320 floats
    __shared__ float4 lut[16];                 // nibble -> 4 spike floats

    if (tid < 16) {
        lut[tid] = make_float4((tid & 1) ? 1.0f : 0.0f,
                               (tid & 2) ? 1.0f : 0.0f,
                               (tid & 4) ? 1.0f : 0.0f,
                               (tid & 8) ? 1.0f : 0.0f);
    }

    // cs[n] = sum over 16 partials, sequential (identical rounding)
    float csn = 0.0f;
#pragma unroll
    for (int oc = 0; oc < OCHUNKS; ++oc) {
        csn = __fadd_rn(csn, g_cs_part[oc * NN + n]);
    }

    const int tseg = s * SEGLEN;
    const float* sxb = g_sx + b * TT;

    for (int i = tid; i < WARM + SEGLEN; i += 128) {
        int g = tseg - WARM + i;
        if (g >= 0) sxs[i] = sxb[g];
    }
    __syncthreads();

    float v = (s == 0) ? v0[n] : 0.0f;

    if (s != 0) {
#pragma unroll 16
        for (int k = 0; k < WARM; ++k) {
            float cur = __fmul_rn(sxs[k], csn);
            v = __fadd_rn(v, __fmul_rn(__fsub_rn(cur, v), 0.1f));
            if (v >= 1.0f) v = 0.0f;
        }
    }

    const int lane = tid & 31;
    const int w    = tid >> 5;
    const int src  = lane >> 3;                // 0..3: row-within-group
    const int j0   = (lane & 7) << 2;          // 0,4,...,28: t offset
    float* outb = out + ((size_t)b * NN + n0) * TT + tseg;

    for (int c8 = 0; c8 < SEGLEN; c8 += TC) {
        unsigned u = 0u;
#pragma unroll
        for (int k = 0; k < TC; ++k) {
            float cur = __fmul_rn(sxs[WARM + c8 + k], csn);
            v = __fadd_rn(v, __fmul_rn(__fsub_rn(cur, v), 0.1f));
            if (v >= 1.0f) { u |= (1u << k); v = 0.0f; }
        }

        // Warp transpose: 8 iterations, each emits one STG.128 (4 t-values
        // of one of this warp's 32 neurons), bits expanded via SMEM LUT.
#pragma unroll
        for (int rr = 0; rr < 8; ++rr) {
            const int rloc = (rr << 2) + src;                  // 0..31
            const unsigned word = __shfl_sync(0xffffffffu, u, rloc);
            const unsigned nib  = (word >> j0) & 0xFu;
            const float4 f = lut[nib];
            const int row = (w << 5) + rloc;                   // 0..127
            *reinterpret_cast<float4*>(outb + (size_t)row * TT + c8 + j0) = f;
        }
    }
}

// ---------------------------------------------------------------------------
extern "C" void kernel_launch(void* const* d_in, const int* in_sizes, int n_in,
                              void* d_out, int out_size) {
    const float* x  = (const float*)d_in[0];
    const float* wt = (const float*)d_in[1];
    const float* v0 = (const float*)d_in[2];
    float* out = (float*)d_out;

    (void)in_sizes; (void)n_in; (void)out_size;

    reduce_fused_kernel<<<192, 256>>>(x, wt);
    lif_seg_kernel<<<dim3(NN / 128, BB, SEG), 128>>>(v0, out);
}